// round 4
// baseline (speedup 1.0000x reference)
#include <cuda_runtime.h>

// Bench shape: N=1024, IND=OUTD=32, E=8192
#define NN    1024
#define DIM   32
#define EMAXP (EBASE + 3 * NN)     // padded-CSR worst case
#define EBASE 8192
#define CHUNK 256
#define NTHR  1024
#define NWARP 32
#define ZROW  (NN * DIM)           // dummy (always-zero) sX row offset

// CSR scratch (device globals: allocation is forbidden)
__device__ int g_offsets[NN + 1];
__device__ int g_colidx[EMAXP];    // col * DIM, rows padded to multiple of 4

// ---- f32x2 packed helpers (Blackwell FFMA2; ptxas won't auto-fuse) --------
__device__ __forceinline__ unsigned long long pack_f2(float lo, float hi) {
    unsigned long long r;
    asm("mov.b64 %0, {%1, %2};" : "=l"(r) : "f"(lo), "f"(hi));
    return r;
}
__device__ __forceinline__ void ffma2(unsigned long long& d,
                                      unsigned long long a,
                                      unsigned long long b) {
    asm("fma.rn.f32x2 %0, %1, %2, %0;" : "+l"(d) : "l"(a), "l"(b));
}
__device__ __forceinline__ float hsum_f2(unsigned long long v) {
    float lo, hi;
    asm("mov.b64 {%0, %1}, %2;" : "=f"(lo), "=f"(hi) : "l"(v));
    return lo + hi;
}

// ---------------------------------------------------------------------------
// Destination-keyed CSR, rows padded to multiples of 4 with dummy index ZROW.
// ---------------------------------------------------------------------------
__global__ void build_csr_kernel(const int* __restrict__ erow,
                                 const int* __restrict__ ecol, int E) {
    __shared__ int scnt[NN];
    __shared__ int sscan[NN];
    __shared__ int scur[NN];
    const int t = threadIdx.x;

    scnt[t] = 0;
    __syncthreads();
    for (int e = t; e < E; e += NN) atomicAdd(&scnt[erow[e]], 1);
    __syncthreads();

    const int padded = (scnt[t] + 3) & ~3;     // round row length up to 4
    sscan[t] = padded;
    __syncthreads();
    #pragma unroll
    for (int d = 1; d < NN; d <<= 1) {
        int x = sscan[t];
        int y = (t >= d) ? sscan[t - d] : 0;
        __syncthreads();
        sscan[t] = x + y;
        __syncthreads();
    }
    const int incl = sscan[t];
    g_offsets[t + 1] = incl;
    if (t == 0) g_offsets[0] = 0;
    scur[t] = incl - padded;
    __syncthreads();

    for (int e = t; e < E; e += NN) {
        int r = erow[e];
        int p = atomicAdd(&scur[r], 1);
        g_colidx[p] = ecol[e] * DIM;
    }
    __syncthreads();
    for (int p = scur[t]; p < incl; p++) g_colidx[p] = ZROW;  // dummy pad
}

// ---------------------------------------------------------------------------
// Fused NGNN conv, aggregation-first:
//   ret[i,j] = m[i,j] * ( (sum_e m[col] X[i,col]) @ W + b * (sum_e m[col]) )
// One CTA per subgraph i, 1024 threads. Masked j skip all work.
// ---------------------------------------------------------------------------
__global__ void __launch_bounds__(NTHR, 1)
ngnn_kernel(const float* __restrict__ X, const int* __restrict__ mask,
            const float* __restrict__ W, const float* __restrict__ b,
            float* __restrict__ out, int E) {
    extern __shared__ float smem[];
    float* sX   = smem;                        // [NN*DIM + DIM] masked X + zero row
    float* sY   = sX + (NN * DIM + DIM);       // [CHUNK*DIM]
    float* smk  = sY + CHUNK * DIM;            // [1056] mask (+ smk[1024]=0)
    float* sc   = smk + 1056;                  // [NN] cnt[j]
    int*   soff = (int*)(sc + NN);             // [1032]
    int*   sidx = soff + 1032;                 // [EMAXP] padded colidx*DIM

    const int tid  = threadIdx.x;
    const int lane = tid & 31;
    const int warp = tid >> 5;
    const int i    = blockIdx.x;

    // W column `lane` packed into f32x2 pairs + bias
    unsigned long long wp[DIM / 2];
    #pragma unroll
    for (int q = 0; q < DIM / 2; q++)
        wp[q] = pack_f2(__ldg(&W[(2 * q) * DIM + lane]),
                        __ldg(&W[(2 * q + 1) * DIM + lane]));
    const float breg = __ldg(&b[lane]);

    // Stage mask + padded CSR into smem; zero the dummy row
    smk[tid] = (float)mask[i * NN + tid];
    if (tid == 0) smk[NN] = 0.0f;              // mask of dummy row
    if (tid < DIM) sX[ZROW + tid] = 0.0f;      // zero row for dummy gathers
    const int EP = g_offsets[NN];              // padded edge count
    for (int t = tid; t <= NN; t += NTHR) soff[t] = g_offsets[t];
    {
        const int4* gci = (const int4*)g_colidx;
        int4* sci = (int4*)sidx;
        for (int q = tid; q < (EP >> 2); q += NTHR) sci[q] = gci[q];
    }
    __syncthreads();

    // Stage X[i] masked; skip the global load entirely when m[k]==0
    {
        const float4* Xg  = (const float4*)(X + (size_t)i * NN * DIM);
        float4* sXv = (float4*)sX;
        #pragma unroll
        for (int q = 0; q < (NN * DIM / 4) / NTHR; q++) {
            int f = tid + q * NTHR;
            float4 v = make_float4(0.f, 0.f, 0.f, 0.f);
            if (smk[f >> 3] != 0.0f) v = Xg[f];    // predicated LDG
            sXv[f] = v;
        }
    }

    // cnt[j] = sum_e m[col]  (thread-per-j; dummies add smk[1024]=0)
    {
        const int s = soff[tid], e = soff[tid + 1];
        float c = 0.0f;
        for (int p = s; p < e; p++) c += smk[sidx[p] >> 5];
        sc[tid] = c;
    }
    __syncthreads();

    // Process j in chunks of CHUNK (sY reuse)
    for (int cb = 0; cb < NN; cb += CHUNK) {
        // ---- Pass A: Y[j] = sum_e sX[col]  (warp-per-j, int4 index loads)
        #pragma unroll 1
        for (int jo = warp; jo < CHUNK; jo += NWARP) {
            const int j = cb + jo;
            if (smk[j] == 0.0f) continue;          // warp-uniform skip
            const int s = soff[j];
            const int e = soff[j + 1];             // e-s multiple of 4
            float a0 = 0.f, a1 = 0.f, a2 = 0.f, a3 = 0.f;
            #pragma unroll 1
            for (int p = s; p < e; p += 4) {
                int4 k = *(const int4*)(sidx + p); // aligned LDS.128
                a0 += sX[k.x + lane];
                a1 += sX[k.y + lane];
                a2 += sX[k.z + lane];
                a3 += sX[k.w + lane];
            }
            sY[jo * DIM + lane] = (a0 + a1) + (a2 + a3);
        }
        __syncthreads();

        // ---- Pass B: MLP on Y via packed f32x2 FMA; zeros for masked j
        #pragma unroll 1
        for (int jo = warp; jo < CHUNK; jo += NWARP) {
            const int j = cb + jo;
            float* o = out + ((size_t)i * NN + j) * DIM + lane;
            if (smk[j] == 0.0f) { *o = 0.0f; continue; }
            const ulonglong2* yr = (const ulonglong2*)(sY + jo * DIM);
            unsigned long long acc0 = 0ULL, acc1 = 0ULL;
            #pragma unroll
            for (int q = 0; q < DIM / 4; q++) {
                ulonglong2 v = yr[q];              // broadcast LDS.128 (2 f32x2)
                ffma2(acc0, v.x, wp[2 * q]);
                ffma2(acc1, v.y, wp[2 * q + 1]);
            }
            *o = fmaf(sc[j], breg, hsum_f2(acc0) + hsum_f2(acc1));
        }
        __syncthreads();   // sY reused next chunk
    }
}

// ---------------------------------------------------------------------------
// Inputs: X, mask, edge_row, edge_col, W, b ; output f32
// ---------------------------------------------------------------------------
extern "C" void kernel_launch(void* const* d_in, const int* in_sizes, int n_in,
                              void* d_out, int out_size) {
    const float* X    = (const float*)d_in[0];
    const int*   mask = (const int*)d_in[1];
    const int*   erow = (const int*)d_in[2];
    const int*   ecol = (const int*)d_in[3];
    const float* W    = (const float*)d_in[4];
    const float* b    = (const float*)d_in[5];
    float*       out  = (float*)d_out;
    const int E = in_sizes[2];

    // floats: sX 32800 + sY 8192 + smk 1056 + sc 1024 ; ints: soff 1032 + sidx EMAXP
    const int smem_bytes = (32800 + 8192 + 1056 + 1024) * 4 + (1032 + EMAXP) * 4;
    cudaFuncSetAttribute(ngnn_kernel,
                         cudaFuncAttributeMaxDynamicSharedMemorySize, smem_bytes);

    build_csr_kernel<<<1, NN>>>(erow, ecol, E);
    ngnn_kernel<<<NN, NTHR, smem_bytes>>>(X, mask, W, b, out, E);
}

// round 5
// speedup vs baseline: 1.0447x; 1.0447x over previous
#include <cuda_runtime.h>

// Bench shape: N=1024, IND=OUTD=32, E=8192
#define NN    1024
#define DIM   32
#define EBASE 8192
#define EMAXP (EBASE + 3 * NN)     // padded-CSR worst case (rows rounded to 4)
#define CHUNK 128
#define NTHR  1024
#define NWARP 32
#define ZROW  (NN * DIM)           // dummy (always-zero) sX row offset

// CSR scratch (device globals: allocation is forbidden)
__device__ int g_offsets[NN + 1];
__device__ int g_colidx[EMAXP];    // col * DIM, rows padded to multiple of 4 (pad -> ZROW)

// ---------------------------------------------------------------------------
// Destination-keyed CSR, rows padded to multiples of 4 with dummy index ZROW.
// ---------------------------------------------------------------------------
__global__ void build_csr_kernel(const int* __restrict__ erow,
                                 const int* __restrict__ ecol, int E) {
    __shared__ int scnt[NN];
    __shared__ int sscan[NN];
    __shared__ int scur[NN];
    const int t = threadIdx.x;

    scnt[t] = 0;
    __syncthreads();
    for (int e = t; e < E; e += NN) atomicAdd(&scnt[erow[e]], 1);
    __syncthreads();

    const int padded = (scnt[t] + 3) & ~3;
    sscan[t] = padded;
    __syncthreads();
    #pragma unroll
    for (int d = 1; d < NN; d <<= 1) {
        int x = sscan[t];
        int y = (t >= d) ? sscan[t - d] : 0;
        __syncthreads();
        sscan[t] = x + y;
        __syncthreads();
    }
    const int incl = sscan[t];
    g_offsets[t + 1] = incl;
    if (t == 0) g_offsets[0] = 0;
    scur[t] = incl - padded;
    __syncthreads();

    for (int e = t; e < E; e += NN) {
        int r = erow[e];
        int p = atomicAdd(&scur[r], 1);
        g_colidx[p] = ecol[e] * DIM;
    }
    __syncthreads();
    for (int p = scur[t]; p < incl; p++) g_colidx[p] = ZROW;
}

// ---------------------------------------------------------------------------
// Fused NGNN conv, aggregation-first + active-list compaction:
//   ret[i,j] = m[i,j] * ( (sum_e m[col] X[i,col]) @ W + b * (sum_e m[col]) )
// One CTA per subgraph i, 1024 threads. Only active j's (m!=0) are processed;
// masked rows are zero-filled by a dedicated vector loop.
// ---------------------------------------------------------------------------
__global__ void __launch_bounds__(NTHR, 1)
ngnn_kernel(const float* __restrict__ X, const int* __restrict__ mask,
            const float* __restrict__ W, const float* __restrict__ b,
            float* __restrict__ out) {
    extern __shared__ float smem[];
    float* sX    = smem;                       // [NN*DIM + DIM]  masked X + zero row
    float* sY    = sX + (NN * DIM + DIM);      // [CHUNK*DIM]
    float* smk   = sY + CHUNK * DIM;           // [1056]  mask (+ smk[1024]=0)
    float* sc    = smk + 1056;                 // [NN]    cnt[j]
    float* sW    = sc + NN;                    // [1024]  W copy
    int*   soff  = (int*)(sW + NN);            // [1032]
    int*   sidx  = soff + 1032;                // [EMAXP] padded colidx*DIM
    int*   alist = sidx + EMAXP;               // [NN] active j list
    int*   mlist = alist + NN;                 // [NN] masked j list
    int*   scnt2 = mlist + NN;                 // [2] {nact, nmask}

    const int tid  = threadIdx.x;
    const int lane = tid & 31;
    const int warp = tid >> 5;
    const int i    = blockIdx.x;

    const float breg = __ldg(&b[lane]);

    // ---- S0: stage mask, W, CSR; init counters & zero row ----
    const int mval = mask[i * NN + tid];
    smk[tid] = (float)mval;
    sW[tid]  = __ldg(&W[tid]);
    if (tid == 0) { smk[NN] = 0.0f; scnt2[0] = 0; scnt2[1] = 0; }
    if (tid < DIM) sX[ZROW + tid] = 0.0f;
    for (int t = tid; t <= NN; t += NTHR) soff[t] = g_offsets[t];
    {
        const int EP = g_offsets[NN];          // padded edge count (mult of 4)
        const int4* gci = (const int4*)g_colidx;
        int4* sci = (int4*)sidx;
        for (int q = tid; q < (EP >> 2); q += NTHR) sci[q] = gci[q];
    }
    __syncthreads();

    // ---- S1: build active/masked lists; stage X masked ----
    {
        const unsigned full = 0xffffffffu;
        const unsigned act = __ballot_sync(full, mval != 0);
        const unsigned lt  = (lane == 0) ? 0u : (0xffffffffu >> (32 - lane));
        int baseA = 0, baseM = 0;
        if (lane == 0) {
            baseA = atomicAdd(&scnt2[0], __popc(act));
            baseM = atomicAdd(&scnt2[1], 32 - __popc(act));
        }
        baseA = __shfl_sync(full, baseA, 0);
        baseM = __shfl_sync(full, baseM, 0);
        if (mval) alist[baseA + __popc(act & lt)] = tid;
        else      mlist[baseM + __popc(~act & lt)] = tid;
    }
    {
        const float4* Xg  = (const float4*)(X + (size_t)i * NN * DIM);
        float4* sXv = (float4*)sX;
        #pragma unroll
        for (int q = 0; q < (NN * DIM / 4) / NTHR; q++) {
            int f = tid + q * NTHR;
            float4 v = make_float4(0.f, 0.f, 0.f, 0.f);
            if (smk[f >> 3] != 0.0f) v = Xg[f];    // predicated LDG
            sXv[f] = v;
        }
    }
    __syncthreads();

    const int nact  = scnt2[0];
    const int nmask = scnt2[1];

    // ---- S2: zero-fill masked output rows; cnt for active j ----
    #pragma unroll 1
    for (int t = tid; t < nmask; t += NTHR) {
        float4* o = (float4*)(out + ((size_t)i * NN + mlist[t]) * DIM);
        const float4 z = make_float4(0.f, 0.f, 0.f, 0.f);
        #pragma unroll
        for (int q = 0; q < 8; q++) o[q] = z;
    }
    #pragma unroll 1
    for (int t = tid; t < nact; t += NTHR) {
        const int j = alist[t];
        const int s = soff[j], e = soff[j + 1];
        float c = 0.0f;
        for (int p = s; p < e; p++) c += smk[sidx[p] >> 5];  // dummies add 0
        sc[j] = c;
    }
    __syncthreads();

    // ---- S3: chunked over the ACTIVE list ----
    for (int cb = 0; cb < nact; cb += CHUNK) {
        const int tEnd = min(cb + CHUNK, nact);

        // Pass A: two active j's per warp, interleaved gathers (8 in flight)
        #pragma unroll 1
        for (int t = cb + warp; t < tEnd; t += 2 * NWARP) {
            const int t2 = t + NWARP;
            const bool has2 = (t2 < tEnd);
            const int jA = alist[t];
            const int sA = soff[jA];
            const int nA = (soff[jA + 1] - sA) >> 2;
            int sB = sA, nB = 0;
            if (has2) { int jB = alist[t2]; sB = soff[jB]; nB = (soff[jB + 1] - sB) >> 2; }
            float a0 = 0.f, a1 = 0.f, a2 = 0.f, a3 = 0.f;
            float c0 = 0.f, c1 = 0.f, c2 = 0.f, c3 = 0.f;
            const int nmx = max(nA, nB);
            #pragma unroll 1
            for (int g = 0; g < nmx; g++) {
                if (g < nA) {
                    int4 k = *(const int4*)(sidx + sA + 4 * g);  // aligned LDS.128
                    a0 += sX[k.x + lane];
                    a1 += sX[k.y + lane];
                    a2 += sX[k.z + lane];
                    a3 += sX[k.w + lane];
                }
                if (g < nB) {
                    int4 k = *(const int4*)(sidx + sB + 4 * g);
                    c0 += sX[k.x + lane];
                    c1 += sX[k.y + lane];
                    c2 += sX[k.z + lane];
                    c3 += sX[k.w + lane];
                }
            }
            sY[(t - cb) * DIM + lane] = (a0 + a1) + (a2 + a3);
            if (has2) sY[(t2 - cb) * DIM + lane] = (c0 + c1) + (c2 + c3);
        }
        __syncthreads();

        // Pass B: MLP on Y chunk. W loaded per chunk (keeps pass-A regs low).
        {
            float wv[DIM];
            #pragma unroll
            for (int d = 0; d < DIM; d++) wv[d] = sW[d * DIM + lane];
            #pragma unroll 1
            for (int t = cb + warp; t < tEnd; t += NWARP) {
                const int j = alist[t];
                const float4* yr = (const float4*)(sY + (t - cb) * DIM);
                float acc0 = sc[j] * breg, acc1 = 0.f, acc2 = 0.f, acc3 = 0.f;
                #pragma unroll
                for (int q = 0; q < DIM / 4; q++) {
                    float4 v = yr[q];                  // broadcast LDS.128
                    acc0 = fmaf(v.x, wv[4 * q + 0], acc0);
                    acc1 = fmaf(v.y, wv[4 * q + 1], acc1);
                    acc2 = fmaf(v.z, wv[4 * q + 2], acc2);
                    acc3 = fmaf(v.w, wv[4 * q + 3], acc3);
                }
                out[((size_t)i * NN + j) * DIM + lane] = (acc0 + acc1) + (acc2 + acc3);
            }
        }
        __syncthreads();   // sY reused next chunk
    }
}

// ---------------------------------------------------------------------------
// Inputs: X, mask, edge_row, edge_col, W, b ; output f32
// ---------------------------------------------------------------------------
extern "C" void kernel_launch(void* const* d_in, const int* in_sizes, int n_in,
                              void* d_out, int out_size) {
    const float* X    = (const float*)d_in[0];
    const int*   mask = (const int*)d_in[1];
    const int*   erow = (const int*)d_in[2];
    const int*   ecol = (const int*)d_in[3];
    const float* W    = (const float*)d_in[4];
    const float* b    = (const float*)d_in[5];
    float*       out  = (float*)d_out;
    const int E = in_sizes[2];

    // floats: sX 32800 + sY 4096 + smk 1056 + sc 1024 + sW 1024 = 40000
    // ints:   soff 1032 + sidx 11264 + alist 1024 + mlist 1024 + 2 = 14346
    const int smem_bytes = 40000 * 4 + 14346 * 4 + 24;   // ~217.4 KB
    cudaFuncSetAttribute(ngnn_kernel,
                         cudaFuncAttributeMaxDynamicSharedMemorySize, smem_bytes);

    build_csr_kernel<<<1, NN>>>(erow, ecol, E);
    ngnn_kernel<<<NN, NTHR, smem_bytes>>>(X, mask, W, b, out);
}

// round 6
// speedup vs baseline: 1.1077x; 1.0603x over previous
#include <cuda_runtime.h>

// Bench shape: N=1024, IND=OUTD=32, E=8192
#define NN    1024
#define DIM   32
#define EBASE 8192
#define EMAXP (EBASE + 3 * NN)     // padded-CSR worst case (rows rounded to 4)
#define CHUNK 256
#define NTHR  1024
#define NWARP 32
#define ZROW  (NN * DIM)           // dummy (always-zero) sX row offset

// Shared-memory layout (float-indexed offsets into one dynamic allocation)
#define OFF_SX   0                 // [32800] masked X rows + zero row
#define OFF_SY   32800             // [CHUNK*DIM = 8192]
#define OFF_SMK  40992             // [1056] mask (+ smk[1024] = 0 for dummies)
#define OFF_SC   42048             // [1024] cnt[j]
#define OFF_SW   43072             // [1024] W copy
#define OFF_SOFF 44096             // [1032] (int) CSR offsets
#define OFF_SIDX 45128             // [EMAXP] (int) padded colidx*DIM
#define SMEM_FLOATS (OFF_SIDX + EMAXP)

extern __shared__ float smem[];

// CSR scratch (device globals: allocation is forbidden)
__device__ int g_offsets[NN + 1];
__device__ int g_colidx[EMAXP];

// ---- f32x2 packed helpers (Blackwell FFMA2; ptxas won't auto-fuse) --------
__device__ __forceinline__ unsigned long long pack_f2(float lo, float hi) {
    unsigned long long r;
    asm("mov.b64 %0, {%1, %2};" : "=l"(r) : "f"(lo), "f"(hi));
    return r;
}
__device__ __forceinline__ void ffma2(unsigned long long& d,
                                      unsigned long long a,
                                      unsigned long long b) {
    asm("fma.rn.f32x2 %0, %1, %2, %0;" : "+l"(d) : "l"(a), "l"(b));
}
__device__ __forceinline__ float hsum_f2(unsigned long long v) {
    float lo, hi;
    asm("mov.b64 {%0, %1}, %2;" : "=f"(lo), "=f"(hi) : "l"(v));
    return lo + hi;
}

// ---------------------------------------------------------------------------
// Destination-keyed CSR, rows padded to multiples of 4 with dummy index ZROW.
// ---------------------------------------------------------------------------
__global__ void build_csr_kernel(const int* __restrict__ erow,
                                 const int* __restrict__ ecol, int E) {
    __shared__ int scnt[NN];
    __shared__ int sscan[NN];
    __shared__ int scur[NN];
    const int t = threadIdx.x;

    scnt[t] = 0;
    __syncthreads();
    for (int e = t; e < E; e += NN) atomicAdd(&scnt[erow[e]], 1);
    __syncthreads();

    const int padded = (scnt[t] + 3) & ~3;
    sscan[t] = padded;
    __syncthreads();
    #pragma unroll
    for (int d = 1; d < NN; d <<= 1) {
        int x = sscan[t];
        int y = (t >= d) ? sscan[t - d] : 0;
        __syncthreads();
        sscan[t] = x + y;
        __syncthreads();
    }
    const int incl = sscan[t];
    g_offsets[t + 1] = incl;
    if (t == 0) g_offsets[0] = 0;
    scur[t] = incl - padded;
    __syncthreads();

    for (int e = t; e < E; e += NN) {
        int r = erow[e];
        int p = atomicAdd(&scur[r], 1);
        g_colidx[p] = ecol[e] * DIM;
    }
    __syncthreads();
    for (int p = scur[t]; p < incl; p++) g_colidx[p] = ZROW;
}

// ---------------------------------------------------------------------------
// Pass A (own register frame): Y[j] = sum_e sX[col]  for one chunk
// ---------------------------------------------------------------------------
__device__ __noinline__ void passA(int cb, int lane, int warp) {
    const float* sX  = smem + OFF_SX;
    const float* smk = smem + OFF_SMK;
    float*       sY  = smem + OFF_SY;
    const int*   soff = (const int*)(smem + OFF_SOFF);
    const int*   sidx = (const int*)(smem + OFF_SIDX);

    #pragma unroll 1
    for (int jo = warp; jo < CHUNK; jo += NWARP) {
        const int j = cb + jo;
        if (smk[j] == 0.0f) continue;          // warp-uniform skip
        const int s = soff[j];
        const int e = soff[j + 1];             // e-s is a multiple of 4
        float a0 = 0.f, a1 = 0.f, a2 = 0.f, a3 = 0.f;
        #pragma unroll 1
        for (int p = s; p < e; p += 4) {
            int4 k = *(const int4*)(sidx + p); // aligned LDS.128
            a0 += sX[k.x + lane];
            a1 += sX[k.y + lane];
            a2 += sX[k.z + lane];
            a3 += sX[k.w + lane];
        }
        sY[jo * DIM + lane] = (a0 + a1) + (a2 + a3);
    }
}

// ---------------------------------------------------------------------------
// Pass B (own register frame): out rows for one chunk via packed f32x2 FMA
// ---------------------------------------------------------------------------
__device__ __noinline__ void passB(float* __restrict__ out, int cb,
                                   int lane, int warp, float breg, int i) {
    const float* sY  = smem + OFF_SY;
    const float* smk = smem + OFF_SMK;
    const float* sc  = smem + OFF_SC;
    const float* sW  = smem + OFF_SW;

    // W column `lane` packed into 16 f32x2 pairs (32 regs, live only here)
    unsigned long long wp[DIM / 2];
    #pragma unroll
    for (int q = 0; q < DIM / 2; q++)
        wp[q] = pack_f2(sW[(2 * q) * DIM + lane], sW[(2 * q + 1) * DIM + lane]);

    #pragma unroll 1
    for (int jo = warp; jo < CHUNK; jo += NWARP) {
        const int j = cb + jo;
        float* o = out + ((size_t)i * NN + j) * DIM + lane;
        if (smk[j] == 0.0f) { *o = 0.0f; continue; }
        const ulonglong2* yr = (const ulonglong2*)(sY + jo * DIM);
        unsigned long long acc0 = 0ULL, acc1 = 0ULL;
        #pragma unroll
        for (int q = 0; q < DIM / 4; q++) {
            ulonglong2 v = yr[q];              // broadcast LDS.128 (2 f32x2)
            ffma2(acc0, v.x, wp[2 * q]);
            ffma2(acc1, v.y, wp[2 * q + 1]);
        }
        *o = fmaf(sc[j], breg, hsum_f2(acc0) + hsum_f2(acc1));
    }
}

// ---------------------------------------------------------------------------
// Fused NGNN conv, aggregation-first:
//   ret[i,j] = m[i,j] * ( (sum_e m[col] X[i,col]) @ W + b * (sum_e m[col]) )
// ---------------------------------------------------------------------------
__global__ void __launch_bounds__(NTHR, 1)
ngnn_kernel(const float* __restrict__ X, const int* __restrict__ mask,
            const float* __restrict__ W, const float* __restrict__ b,
            float* __restrict__ out) {
    float* sX  = smem + OFF_SX;
    float* smk = smem + OFF_SMK;
    float* sc  = smem + OFF_SC;
    float* sW  = smem + OFF_SW;
    int*   soff = (int*)(smem + OFF_SOFF);
    int*   sidx = (int*)(smem + OFF_SIDX);

    const int tid  = threadIdx.x;
    const int lane = tid & 31;
    const int warp = tid >> 5;
    const int i    = blockIdx.x;

    const float breg = __ldg(&b[lane]);

    // ---- Stage mask, W, padded CSR; zero row for dummy gathers ----
    smk[tid] = (float)mask[i * NN + tid];
    sW[tid]  = __ldg(&W[tid]);
    if (tid == 0) smk[NN] = 0.0f;              // mask of dummy row
    if (tid < DIM) sX[ZROW + tid] = 0.0f;
    for (int t = tid; t <= NN; t += NTHR) soff[t] = g_offsets[t];
    {
        const int EP = g_offsets[NN];          // padded edge count (mult of 4)
        const int4* gci = (const int4*)g_colidx;
        int4* sci = (int4*)sidx;
        for (int q = tid; q < (EP >> 2); q += NTHR) sci[q] = gci[q];
    }
    __syncthreads();

    // ---- Stage X[i] masked; skip the global load when m[k]==0 ----
    {
        const float4* Xg  = (const float4*)(X + (size_t)i * NN * DIM);
        float4* sXv = (float4*)sX;
        #pragma unroll
        for (int q = 0; q < (NN * DIM / 4) / NTHR; q++) {
            int f = tid + q * NTHR;
            float4 v = make_float4(0.f, 0.f, 0.f, 0.f);
            if (smk[f >> 3] != 0.0f) v = Xg[f];    // predicated LDG
            sXv[f] = v;
        }
    }

    // ---- cnt[j] = sum_e m[col]  (thread-per-j; dummies add smk[1024]=0) ----
    {
        const int s = soff[tid], e = soff[tid + 1];
        float c = 0.0f;
        for (int p = s; p < e; p++) c += smk[sidx[p] >> 5];
        sc[tid] = c;
    }
    __syncthreads();

    // ---- Chunked aggregate + MLP ----
    for (int cb = 0; cb < NN; cb += CHUNK) {
        passA(cb, lane, warp);
        __syncthreads();
        passB(out, cb, lane, warp, breg, i);
        __syncthreads();   // sY reused next chunk
    }
}

// ---------------------------------------------------------------------------
// Inputs: X, mask, edge_row, edge_col, W, b ; output f32
// ---------------------------------------------------------------------------
extern "C" void kernel_launch(void* const* d_in, const int* in_sizes, int n_in,
                              void* d_out, int out_size) {
    const float* X    = (const float*)d_in[0];
    const int*   mask = (const int*)d_in[1];
    const int*   erow = (const int*)d_in[2];
    const int*   ecol = (const int*)d_in[3];
    const float* W    = (const float*)d_in[4];
    const float* b    = (const float*)d_in[5];
    float*       out  = (float*)d_out;
    const int E = in_sizes[2];

    const int smem_bytes = SMEM_FLOATS * 4;    // ~220 KB
    cudaFuncSetAttribute(ngnn_kernel,
                         cudaFuncAttributeMaxDynamicSharedMemorySize, smem_bytes);

    build_csr_kernel<<<1, NN>>>(erow, ecol, E);
    ngnn_kernel<<<NN, NTHR, smem_bytes>>>(X, mask, W, b, out);
}